// round 7
// baseline (speedup 1.0000x reference)
#include <cuda_runtime.h>
#include <stdint.h>

#define QIN   90
#define QOUT  60
#define OPAD  64
#define KMAX  16
#define CINV  32
#define COUTV 32
#define H1V   32
#define H2V   64
#define DMAXV 1.0f
#define MAXB  4
#define ROWF  (QIN * CINV)   // 2880 floats per (b,n) row
#define NRB   8              // rows per iteration
#define NTH   512
#define FB_FLOATS (2 * NRB * ROWF)
#define AG_FLOATS (NRB * 32 * CINV)
#define WF_FLOATS (CINV * COUTV)
#define SMEM_BYTES ((FB_FLOATS + AG_FLOATS + WF_FLOATS) * 4)

typedef unsigned long long ull;
// packed f32x2 FMA: acc = a*b + acc (elementwise on two packed floats)
#define FFMA2(acc, a, b) \
    asm("fma.rn.f32x2 %0, %1, %2, %0;" : "+l"(acc) : "l"(a), "l"(b))

// Per-(b,o) compacted tables produced by prep_kernel.
__device__ float          g_Mw[MAXB * OPAD * KMAX * CINV];  // [b][o][k][c], masked weights
__device__ unsigned short g_selo[MAXB * OPAD * KMAX];       // [b][o][k], BYTE offset i*128

// ---------------------------------------------------------------------------
// Kernel 1: distances + top-K selection + WeightNet MLP -> compact tables
// ---------------------------------------------------------------------------
__global__ void prep_kernel(const float* __restrict__ ang_in, const float* __restrict__ ang_out,
                            const float* __restrict__ W1, const float* __restrict__ b1,
                            const float* __restrict__ W2, const float* __restrict__ b2,
                            const float* __restrict__ W3, const float* __restrict__ b3,
                            int B)
{
    int bo = blockIdx.x;
    int b = bo / OPAD, o = bo % OPAD;
    int tid = threadIdx.x;

    if (o >= QOUT) {  // padded o slots: zero weights so main kernel adds nothing
        for (int i = tid; i < KMAX * CINV; i += blockDim.x)
            g_Mw[(b * OPAD + o) * KMAX * CINV + i] = 0.f;
        if (tid < KMAX) g_selo[(b * OPAD + o) * KMAX + tid] = 0;
        return;
    }

    __shared__ float sd[QIN], sbd[QIN];
    __shared__ int   ssel[KMAX];
    __shared__ float smask[KMAX], skd[KMAX], skbd[KMAX];
    __shared__ float sW2[H1V * H2V], sW3[H2V * CINV];
    __shared__ float sW1a[H1V], sW1b[H1V], sb1[H1V], sb2[H2V], sb3[CINV];
    __shared__ float sh1[KMAX][H1V], sh2[KMAX][H2V];

    for (int i = tid; i < H1V * H2V; i += 128) sW2[i] = W2[i];
    for (int i = tid; i < H2V * CINV; i += 128) sW3[i] = W3[i];
    if (tid < H2V) sb2[tid] = b2[tid];
    if (tid < CINV) sb3[tid] = b3[tid];
    if (tid < H1V) { sW1a[tid] = W1[3 * H1V + tid]; sW1b[tid] = W1[4 * H1V + tid]; sb1[tid] = b1[tid]; }

    float aox = ang_out[(b * QOUT + o) * 3 + 0];
    float aoy = ang_out[(b * QOUT + o) * 3 + 1];
    float aoz = ang_out[(b * QOUT + o) * 3 + 2];
    float nout = sqrtf(aox * aox + aoy * aoy + aoz * aoz);
    float ivo = (nout > 0.f) ? 1.f / nout : 0.f;
    float uox = aox * ivo, uoy = aoy * ivo, uoz = aoz * ivo;

    if (tid < QIN) {
        float x = ang_in[(b * QIN + tid) * 3 + 0];
        float y = ang_in[(b * QIN + tid) * 3 + 1];
        float z = ang_in[(b * QIN + tid) * 3 + 2];
        float nin = sqrtf(x * x + y * y + z * z);
        float ivi = (nin > 0.f) ? 1.f / nin : 0.f;
        float dot = (x * ivi) * uox + (y * ivi) * uoy + (z * ivi) * uoz;
        float d = acosf(fminf(fabsf(dot), 1.0f - 1e-7f));
        sd[tid] = d;
        sbd[tid] = nout - nin;
    }
    __syncthreads();

    if (tid < QIN) {
        float dt = sd[tid];
        int r = 0;
        for (int j = 0; j < QIN; j++) {
            float dj = sd[j];
            r += (dj < dt || (dj == dt && j < tid)) ? 1 : 0;
        }
        if (r < KMAX) {
            ssel[r] = tid;
            smask[r] = (dt <= DMAXV) ? 1.f : 0.f;
            skd[r] = dt;
            skbd[r] = sbd[tid];
        }
    }
    __syncthreads();

    int k = tid >> 3, ln = tid & 7;
    {
        float d = skd[k], bd = skbd[k];
        #pragma unroll
        for (int jj = 0; jj < 4; jj++) {
            int j = ln * 4 + jj;
            float h = fmaf(d, sW1a[j], fmaf(bd, sW1b[j], sb1[j]));
            sh1[k][j] = fmaxf(h, 0.f);
        }
    }
    __syncthreads();
    #pragma unroll
    for (int ll = 0; ll < 8; ll++) {
        int l = ln * 8 + ll;
        float acc = sb2[l];
        #pragma unroll 8
        for (int j = 0; j < H1V; j++) acc = fmaf(sh1[k][j], sW2[j * H2V + l], acc);
        sh2[k][l] = fmaxf(acc, 0.f);
    }
    __syncthreads();
    float m = smask[k];
    #pragma unroll
    for (int cc = 0; cc < 4; cc++) {
        int c = ln * 4 + cc;
        float acc = sb3[c];
        #pragma unroll 8
        for (int l = 0; l < H2V; l++) acc = fmaf(sh2[k][l], sW3[l * CINV + c], acc);
        g_Mw[((b * OPAD + o) * KMAX + k) * CINV + c] = m * acc;
    }
    if (ln == 0) g_selo[(b * OPAD + o) * KMAX + k] = (unsigned short)(ssel[k] * (CINV * 4));
}

// ---------------------------------------------------------------------------
// Kernel 2: persistent gather-conv + Wf epilogue, packed f32x2 datapath.
//   1 CTA/SM (512 thr, 16 warps), gridDim.y = 2 o-halves.
//   Warp covers 2 o's: half-warp = one o, lane = channel PAIR (2hl, 2hl+1).
//   ONE block barrier per batch: aggs traffic is half-warp-private, so only
//   the fbuf double buffer needs block-level protection. cp.async issued at
//   distance 2 (into the buffer just consumed) right after the barrier.
// ---------------------------------------------------------------------------
__device__ __forceinline__ void async_rows(float* dst, const float* __restrict__ src,
                                           int nr, int tid)
{
    uint32_t s = (uint32_t)__cvta_generic_to_shared(dst);
    int total = nr * (ROWF / 4);   // float4 count, up to 5760
    #pragma unroll
    for (int i = 0; i < 12; i++) {
        int idx = tid + i * NTH;
        if (idx < total)
            asm volatile("cp.async.cg.shared.global [%0], [%1], 16;\n"
                         :: "r"(s + idx * 16), "l"(src + idx * 4) : "memory");
    }
    asm volatile("cp.async.commit_group;\n" ::: "memory");
}

// Phase 1: gather-reduce, always full NRB rows (stale tail rows are computed
// but their stores to gmem are guarded off in phase 2).
__device__ __forceinline__ void phase1(const char* __restrict__ fbc, float* __restrict__ aggs,
                                       const ull (&Mp)[16], const uint32_t (&ip)[8],
                                       int ogl, int hl)
{
    ull acc[NRB];
    #pragma unroll
    for (int r = 0; r < NRB; r++) acc[r] = 0ULL;

    #pragma unroll
    for (int k = 0; k < 16; k++) {
        int off = (int)((ip[k >> 1] >> ((k & 1) * 16)) & 0xFFFFu);
        const char* p = fbc + off + hl * 8;
        ull m = Mp[k];
        #pragma unroll
        for (int r = 0; r < NRB; r++) {
            ull v = *(const ull*)(p + r * (ROWF * 4));   // LDS.64
            FFMA2(acc[r], m, v);
        }
    }
    #pragma unroll
    for (int r = 0; r < NRB; r++)
        *(ull*)(aggs + (r * 32 + ogl) * CINV + 2 * hl) = acc[r];   // STS.64
}

__global__ void __launch_bounds__(NTH, 1)
conv_kernel(const float* __restrict__ f_in, const float* __restrict__ Wf,
            const float* __restrict__ bias_out, float* __restrict__ out,
            int B, int N)
{
    extern __shared__ float smem[];
    float* fbuf = smem;                             // [2][NRB * ROWF]
    float* aggs = smem + FB_FLOATS;                 // [NRB][32][CINV]
    float* sWf  = smem + FB_FLOATS + AG_FLOATS;     // [CINV][COUTV]

    const int tid   = threadIdx.x;
    const int lane  = tid & 31;
    const int warp  = tid >> 5;          // 0..15
    const int ho    = lane >> 4;         // which o of the warp's pair
    const int hl    = lane & 15;         // channel-pair index (c = 2hl, 2hl+1)
    const int obase = blockIdx.y * 32;   // this block's o-half
    const int ogl   = warp * 2 + ho;     // local o 0..31

    for (int i = tid; i < WF_FLOATS; i += NTH) sWf[i] = Wf[i];
    const float2 bias2 = ((const float2*)bias_out)[hl];

    long long R = (long long)B * N;
    long long chunk = (R + gridDim.x - 1) / gridDim.x;
    long long r0 = (long long)blockIdx.x * chunk;
    long long r1 = r0 + chunk; if (r1 > R) r1 = R;
    if (r0 >= r1) return;

    ull      Mp[16];
    uint32_t ip[8];

    long long g = r0;
    while (g < r1) {
        int b = (int)(g / N);
        long long gend = (long long)(b + 1) * N; if (gend > r1) gend = r1;

        // Per-batch tables: weights as native float2 (per-channel pair), u16 offsets.
        {
            int og = obase + ogl;
            const ull* mp = (const ull*)(g_Mw + (size_t)(b * OPAD + og) * KMAX * CINV);
            #pragma unroll
            for (int k = 0; k < 16; k++) Mp[k] = mp[k * (CINV / 2) + hl];
            const uint32_t* q = (const uint32_t*)&g_selo[(b * OPAD + og) * KMAX];
            #pragma unroll
            for (int j = 0; j < 8; j++) ip[j] = q[j];
        }

        // Preload first two batches (distance-2 pipeline).
        {
            long long nb = gend - g;
            async_rows(fbuf, f_in + g * ROWF, (int)(nb < NRB ? nb : NRB), tid);
            if (nb > NRB) {
                long long n2 = nb - NRB;
                async_rows(fbuf + NRB * ROWF, f_in + (g + NRB) * ROWF,
                           (int)(n2 < NRB ? n2 : NRB), tid);
            }
        }

        int pb = 0;
        for (long long t = g; t < gend; t += NRB, pb ^= 1) {
            // Wait for the group that fills fbuf[pb]. If a later group exists
            // (issued iff t+NRB < gend), allow it to stay outstanding.
            if (t + NRB < gend) {
                asm volatile("cp.async.wait_group 1;\n" ::: "memory");
            } else {
                asm volatile("cp.async.wait_group 0;\n" ::: "memory");
            }
            __syncthreads();   // fbuf[pb] visible to all; prior readers of fbuf[pb] long done

            const int nrows = (int)((gend - t) < NRB ? (gend - t) : NRB);

            phase1((const char*)(fbuf + pb * (NRB * ROWF)), aggs, Mp, ip, ogl, hl);
            __syncwarp();      // aggs produced/consumed within the same half-warp

            // Phase 2: out[og, 2hl..2hl+1] = bias + sum_c' agg[og][c'] * Wf[c'][2hl..]
            float ax[NRB], ay[NRB];
            #pragma unroll
            for (int r = 0; r < NRB; r++) { ax[r] = bias2.x; ay[r] = bias2.y; }

            const float* arow = aggs + ogl * CINV;
            #pragma unroll
            for (int cq = 0; cq < 8; cq++) {
                float2 w0 = ((const float2*)(sWf + (cq * 4 + 0) * COUTV))[hl];
                float2 w1 = ((const float2*)(sWf + (cq * 4 + 1) * COUTV))[hl];
                float2 w2 = ((const float2*)(sWf + (cq * 4 + 2) * COUTV))[hl];
                float2 w3 = ((const float2*)(sWf + (cq * 4 + 3) * COUTV))[hl];
                #pragma unroll
                for (int r = 0; r < NRB; r++) {
                    float4 a4 = *(const float4*)(arow + r * (32 * CINV) + cq * 4); // LDS.128 bcast
                    ax[r] = fmaf(a4.x, w0.x, ax[r]);  ay[r] = fmaf(a4.x, w0.y, ay[r]);
                    ax[r] = fmaf(a4.y, w1.x, ax[r]);  ay[r] = fmaf(a4.y, w1.y, ay[r]);
                    ax[r] = fmaf(a4.z, w2.x, ax[r]);  ay[r] = fmaf(a4.z, w2.y, ay[r]);
                    ax[r] = fmaf(a4.w, w3.x, ax[r]);  ay[r] = fmaf(a4.w, w3.y, ay[r]);
                }
            }

            const int og = obase + ogl;
            if (og < QOUT) {
                #pragma unroll
                for (int r = 0; r < NRB; r++) {
                    if (r < nrows) {
                        float2 v; v.x = ax[r]; v.y = ay[r];
                        *(float2*)(out + (t + r) * (QOUT * COUTV) + og * COUTV + 2 * hl) = v;
                    }
                }
            }

            // All warps have finished reading fbuf[pb] (phase 1 above) before
            // anyone refills it for batch t + 2*NRB.
            __syncthreads();
            long long tn2 = t + 2 * NRB;
            if (tn2 < gend) {
                long long n2 = gend - tn2;
                async_rows(fbuf + pb * (NRB * ROWF), f_in + tn2 * ROWF,
                           (int)(n2 < NRB ? n2 : NRB), tid);
            }
        }
        g = gend;
    }
}

// ---------------------------------------------------------------------------
extern "C" void kernel_launch(void* const* d_in, const int* in_sizes, int n_in,
                              void* d_out, int out_size)
{
    const float* ang_in   = (const float*)d_in[0];
    const float* ang_out  = (const float*)d_in[1];
    const float* f_in     = (const float*)d_in[2];
    const float* W1       = (const float*)d_in[3];
    const float* b1       = (const float*)d_in[4];
    const float* W2       = (const float*)d_in[5];
    const float* b2       = (const float*)d_in[6];
    const float* W3       = (const float*)d_in[7];
    const float* b3       = (const float*)d_in[8];
    const float* Wf       = (const float*)d_in[9];
    const float* bias_out = (const float*)d_in[10];
    float* out = (float*)d_out;

    int B = in_sizes[0] / (QIN * 3);
    int N = in_sizes[2] / (B * QIN * CINV);

    cudaFuncSetAttribute(conv_kernel, cudaFuncAttributeMaxDynamicSharedMemorySize, SMEM_BYTES);

    prep_kernel<<<B * OPAD, 128>>>(ang_in, ang_out, W1, b1, W2, b2, W3, b3, B);

    int nsm = 148;
    cudaDeviceGetAttribute(&nsm, cudaDevAttrMultiProcessorCount, 0);
    int gx = nsm / 2; if (gx < 1) gx = 1;
    dim3 grid(gx, 2);
    conv_kernel<<<grid, NTH, SMEM_BYTES>>>(f_in, Wf, bias_out, out, B, N);
}